// round 3
// baseline (speedup 1.0000x reference)
#include <cuda_runtime.h>

// ObservabilityWeightedMSE — fully fused single-kernel weighted-MSE reduction.
// d_in[0]=predictions [500000,82] f32, d_in[1]=targets [500000,82] f32,
// d_in[2]=inputs [500000,400] f32. Output: scalar f32.

#define THRESH   1e-4f
#define NCOLS    82
#define ROW_IN   400
#define NBLOCKS  1184
#define NTHREADS 256

__device__ float        g_part[NBLOCKS];
__device__ unsigned int g_count = 0;   // self-resetting across calls

__global__ void __launch_bounds__(NTHREADS)
wmse_kernel(const float* __restrict__ pred,
            const float* __restrict__ targ,
            const float* __restrict__ inp,
            int B, double inv_total, float* __restrict__ out)
{
    const int lane  = threadIdx.x & 31;
    const int warp  = threadIdx.x >> 5;
    const int gwarp = blockIdx.x * (NTHREADS / 32) + warp;
    const int nwarp = NBLOCKS * (NTHREADS / 32);

    // ---- lane-constant geometry (hoisted) ----
    const int  n0 = lane / 5, p0 = lane % 5;          // inputs float4 #0 (idx = lane)
    const int  i1 = 32 + lane;
    const int  n1 = i1 / 5,  p1 = i1 % 5;             // inputs float4 #1 (idx = 32+lane)
    const bool has1  = (i1 < 50);                     // lanes 0..17
    const bool hasJ1 = (lane < 9);                    // float2 idx 32+lane < 41
    const int  off0  = n0 * 40 + p0 * 4;
    const int  off1  = n1 * 40 + p1 * 4;

    // ---- lane-constant spatial-mask weights (hoisted out of row loop) ----
    // columns handled by this lane: c0=2*lane, c1=2*lane+1, c2=64+2*lane, c3=65+2*lane
    float wb[4]; int kc[4];
    {
        int cs[4] = {2 * lane, 2 * lane + 1, 64 + 2 * lane, 65 + 2 * lane};
        #pragma unroll
        for (int q = 0; q < 4; ++q) {
            int c = cs[q];
            bool five; int col;
            if (c < 41) { col = c; five = ((c & 3) == 0); }
            else {
                int j = c - 41; col = j;
                five = ((j & 3) == 3) || (((j & 3) == 0) && (j != 40));
            }
            wb[q] = five ? 5.0f : 1.0f;
            kc[q] = col;
        }
    }

    float acc = 0.0f;

    for (int r = gwarp; r < B; r += nwarp) {
        const float* pin = inp  + (size_t)r * ROW_IN;
        const float* pp  = pred + (size_t)r * NCOLS;
        const float* pt  = targ + (size_t)r * NCOLS;

        // ---- front-batch ALL loads for this row before the warp sync ----
        float4 a0 = *(const float4*)(pin + off0);
        float4 a1 = make_float4(0.f, 0.f, 0.f, 0.f);
        if (has1) a1 = *(const float4*)(pin + off1);

        float2 p0v = ((const float2*)pp)[lane];
        float2 t0v = ((const float2*)pt)[lane];
        float2 p1v = make_float2(0.f, 0.f), t1v = make_float2(0.f, 0.f);
        if (hasJ1) {
            p1v = ((const float2*)pp)[32 + lane];
            t1v = ((const float2*)pt)[32 + lane];
        }

        // ---- node-below bits -> stage cutoff ----
        unsigned ok = 0;
        if (a0.x >= THRESH || a0.y >= THRESH || a0.z >= THRESH || a0.w >= THRESH)
            ok = 1u << n0;
        if (has1 && (a1.x >= THRESH || a1.y >= THRESH || a1.z >= THRESH || a1.w >= THRESH))
            ok |= 1u << n1;
        unsigned below = (~__reduce_or_sync(0xffffffffu, ok)) & 0x3FFu;
        const int cut = below ? (__ffs(below) << 2) : 1000;

        // ---- weighted MSE (weights: hoisted base * optional 0.1) ----
        float w0 = (kc[0] >= cut) ? wb[0] * 0.1f : wb[0];
        float w1 = (kc[1] >= cut) ? wb[1] * 0.1f : wb[1];
        float d  = p0v.x - t0v.x; acc = fmaf(d * d, w0, acc);
        d        = p0v.y - t0v.y; acc = fmaf(d * d, w1, acc);
        if (hasJ1) {
            float w2 = (kc[2] >= cut) ? wb[2] * 0.1f : wb[2];
            float w3 = (kc[3] >= cut) ? wb[3] * 0.1f : wb[3];
            d = p1v.x - t1v.x; acc = fmaf(d * d, w2, acc);
            d = p1v.y - t1v.y; acc = fmaf(d * d, w3, acc);
        }
    }

    // ---- block reduction ----
    #pragma unroll
    for (int o = 16; o > 0; o >>= 1)
        acc += __shfl_down_sync(0xffffffffu, acc, o);

    __shared__ float smem[NTHREADS / 32];
    __shared__ bool  s_last;
    if (lane == 0) smem[warp] = acc;
    __syncthreads();
    if (warp == 0) {
        float v = (lane < (NTHREADS / 32)) ? smem[lane] : 0.0f;
        #pragma unroll
        for (int o = 4; o > 0; o >>= 1)
            v += __shfl_down_sync(0xffffffffu, v, o);
        if (lane == 0) {
            g_part[blockIdx.x] = v;
            __threadfence();                       // publish partial
            unsigned n = atomicAdd(&g_count, 1u);  // arrival
            s_last = (n == NBLOCKS - 1);
        }
    }
    __syncthreads();

    // ---- last block: deterministic final reduction in double ----
    if (s_last) {
        __threadfence();  // acquire all partials
        double a = 0.0;
        for (int i = threadIdx.x; i < NBLOCKS; i += NTHREADS)
            a += (double)((volatile float*)g_part)[i];
        #pragma unroll
        for (int o = 16; o > 0; o >>= 1)
            a += __shfl_down_sync(0xffffffffu, a, o);
        __shared__ double sd[NTHREADS / 32];
        if (lane == 0) sd[warp] = a;
        __syncthreads();
        if (warp == 0) {
            a = (lane < (NTHREADS / 32)) ? sd[lane] : 0.0;
            #pragma unroll
            for (int o = 4; o > 0; o >>= 1)
                a += __shfl_down_sync(0xffffffffu, a, o);
            if (lane == 0) {
                out[0]  = (float)(a * inv_total);
                g_count = 0;                       // reset for next graph replay
            }
        }
    }
}

extern "C" void kernel_launch(void* const* d_in, const int* in_sizes, int n_in,
                              void* d_out, int out_size)
{
    const float* pred = (const float*)d_in[0];
    const float* targ = (const float*)d_in[1];
    const float* inp  = (const float*)d_in[2];
    float* out = (float*)d_out;

    const int B = in_sizes[0] / NCOLS;   // 500000

    wmse_kernel<<<NBLOCKS, NTHREADS>>>(pred, targ, inp, B,
                                       1.0 / ((double)B * NCOLS), out);
}

// round 4
// speedup vs baseline: 1.0023x; 1.0023x over previous
#include <cuda_runtime.h>

// ObservabilityWeightedMSE — fused single-kernel weighted-MSE reduction.
// d_in[0]=predictions [500000,82] f32, d_in[1]=targets [500000,82] f32,
// d_in[2]=inputs [500000,400] f32. Output: scalar f32.
// Key constraint discovered R3: this kernel is occupancy-bound; keep the hot
// loop's live state minimal (<=32 regs) so 8 blocks/SM stay resident.

#define THRESH   1e-4f
#define NCOLS    82
#define ROW_IN   400
#define NBLOCKS  1184
#define NTHREADS 256

__device__ float        g_part[NBLOCKS];
__device__ unsigned int g_count = 0;   // self-resetting each call

__global__ void __launch_bounds__(NTHREADS, 8)   // force <=32 regs: 8 blocks/SM
wmse_kernel(const float* __restrict__ pred,
            const float* __restrict__ targ,
            const float* __restrict__ inp,
            int B, double inv_total, float* __restrict__ out)
{
    const int lane  = threadIdx.x & 31;
    const int warp  = threadIdx.x >> 5;
    const int gwarp = blockIdx.x * (NTHREADS / 32) + warp;
    const int nwarp = NBLOCKS * (NTHREADS / 32);

    // lane-constant geometry for the inputs magnitude slice
    const int  n0   = lane / 5, p0 = lane % 5;      // float4 idx = lane
    const int  i1   = 32 + lane;
    const int  n1   = i1 / 5,  p1 = i1 % 5;         // float4 idx = 32+lane
    const bool has1 = (i1 < 50);                    // lanes 0..17
    const int  off0 = n0 * 40 + p0 * 4;
    const int  off1 = n1 * 40 + p1 * 4;

    float acc = 0.0f;

    for (int r = gwarp; r < B; r += nwarp) {
        const float* pin = inp + (size_t)r * ROW_IN;

        // ---- inputs: 20 magnitudes per node, node below <=> all < THRESH ----
        float4 a0 = __ldcs((const float4*)(pin + off0));
        unsigned ok = 0;
        if (a0.x >= THRESH || a0.y >= THRESH || a0.z >= THRESH || a0.w >= THRESH)
            ok = 1u << n0;
        if (has1) {
            float4 a1 = __ldcs((const float4*)(pin + off1));
            if (a1.x >= THRESH || a1.y >= THRESH || a1.z >= THRESH || a1.w >= THRESH)
                ok |= 1u << n1;
        }
        unsigned below = (~__reduce_or_sync(0xffffffffu, ok)) & 0x3FFu;
        const int cut = below ? (__ffs(below) << 2) : 1000;

        // ---- weighted MSE over 82 columns, coalesced scalar loads ----
        const float* pp = pred + (size_t)r * NCOLS;
        const float* pt = targ + (size_t)r * NCOLS;
        #pragma unroll
        for (int it = 0; it < 3; ++it) {
            int c = it * 32 + lane;
            if (c < NCOLS) {
                float d = __ldcs(pp + c) - __ldcs(pt + c);
                bool five; int col;
                if (c < 41) { col = c; five = ((c & 3) == 0); }
                else {
                    int j = c - 41; col = j;
                    five = ((j & 3) == 3) || (((j & 3) == 0) && (j != 40));
                }
                float w = five ? 5.0f : 1.0f;
                if (col >= cut) w *= 0.1f;
                acc = fmaf(d * d, w, acc);
            }
        }
    }

    // ---- block reduction ----
    #pragma unroll
    for (int o = 16; o > 0; o >>= 1)
        acc += __shfl_down_sync(0xffffffffu, acc, o);

    __shared__ float smem[NTHREADS / 32];
    __shared__ bool  s_last;
    if (lane == 0) smem[warp] = acc;
    __syncthreads();
    if (warp == 0) {
        float v = (lane < (NTHREADS / 32)) ? smem[lane] : 0.0f;
        #pragma unroll
        for (int o = 4; o > 0; o >>= 1)
            v += __shfl_down_sync(0xffffffffu, v, o);
        if (lane == 0) {
            g_part[blockIdx.x] = v;
            __threadfence();
            unsigned n = atomicAdd(&g_count, 1u);
            s_last = (n == NBLOCKS - 1);
        }
    }
    __syncthreads();

    // ---- last block: deterministic final reduction (cold path; spills OK) ----
    if (s_last) {
        __threadfence();
        double a = 0.0;
        for (int i = threadIdx.x; i < NBLOCKS; i += NTHREADS)
            a += (double)((volatile float*)g_part)[i];
        #pragma unroll
        for (int o = 16; o > 0; o >>= 1)
            a += __shfl_down_sync(0xffffffffu, a, o);
        __shared__ double sd[NTHREADS / 32];
        if (lane == 0) sd[warp] = a;
        __syncthreads();
        if (warp == 0) {
            a = (lane < (NTHREADS / 32)) ? sd[lane] : 0.0;
            #pragma unroll
            for (int o = 4; o > 0; o >>= 1)
                a += __shfl_down_sync(0xffffffffu, a, o);
            if (lane == 0) {
                out[0]  = (float)(a * inv_total);
                g_count = 0;
            }
        }
    }
}

extern "C" void kernel_launch(void* const* d_in, const int* in_sizes, int n_in,
                              void* d_out, int out_size)
{
    const float* pred = (const float*)d_in[0];
    const float* targ = (const float*)d_in[1];
    const float* inp  = (const float*)d_in[2];
    float* out = (float*)d_out;

    const int B = in_sizes[0] / NCOLS;   // 500000

    wmse_kernel<<<NBLOCKS, NTHREADS>>>(pred, targ, inp, B,
                                       1.0 / ((double)B * NCOLS), out);
}

// round 5
// speedup vs baseline: 1.0035x; 1.0012x over previous
#include <cuda_runtime.h>

// ObservabilityWeightedMSE — fused single-kernel weighted-MSE reduction.
// d_in[0]=predictions [500000,82] f32, d_in[1]=targets [500000,82] f32,
// d_in[2]=inputs [500000,400] f32. Output: scalar f32.
// R3 lesson: occupancy-bound at >32 regs -> __launch_bounds__(256,8).
// R4 lesson: __ldcs evict-first kills row-boundary L1/L2 reuse -> plain loads.

#define THRESH   1e-4f
#define NCOLS    82
#define ROW_IN   400
#define NBLOCKS  1184
#define NTHREADS 256

__device__ float        g_part[NBLOCKS];
__device__ unsigned int g_count = 0;   // self-resetting each call

__global__ void __launch_bounds__(NTHREADS, 8)   // cap regs at 32: 8 blocks/SM
wmse_kernel(const float* __restrict__ pred,
            const float* __restrict__ targ,
            const float* __restrict__ inp,
            int B, double inv_total, float* __restrict__ out)
{
    const int lane  = threadIdx.x & 31;
    const int warp  = threadIdx.x >> 5;
    const int gwarp = blockIdx.x * (NTHREADS / 32) + warp;
    const int nwarp = NBLOCKS * (NTHREADS / 32);

    // lane-constant geometry for the inputs magnitude slice
    const int  n0   = lane / 5, p0 = lane % 5;      // float4 idx = lane
    const int  i1   = 32 + lane;
    const int  n1   = i1 / 5,  p1 = i1 % 5;         // float4 idx = 32+lane
    const bool has1 = (i1 < 50);                    // lanes 0..17
    const int  off0 = n0 * 40 + p0 * 4;
    const int  off1 = n1 * 40 + p1 * 4;

    float acc = 0.0f;

    for (int r = gwarp; r < B; r += nwarp) {
        const float* pin = inp + (size_t)r * ROW_IN;

        // ---- node-below test: below[n] <=> max of 20 magnitudes < THRESH ----
        // ok-bit set <=> any of this lane's 4 values >= THRESH (fmax tree, fma pipe)
        float4 a0 = *(const float4*)(pin + off0);
        unsigned ok = 0;
        if (fmaxf(fmaxf(a0.x, a0.y), fmaxf(a0.z, a0.w)) >= THRESH)
            ok = 1u << n0;
        if (has1) {
            float4 a1 = *(const float4*)(pin + off1);
            if (fmaxf(fmaxf(a1.x, a1.y), fmaxf(a1.z, a1.w)) >= THRESH)
                ok |= 1u << n1;
        }
        unsigned below = (~__reduce_or_sync(0xffffffffu, ok)) & 0x3FFu;
        const int cut = below ? (__ffs(below) << 2) : 1000;

        // ---- weighted MSE over 82 columns, coalesced scalar loads ----
        const float* pp = pred + (size_t)r * NCOLS;
        const float* pt = targ + (size_t)r * NCOLS;
        #pragma unroll
        for (int it = 0; it < 3; ++it) {
            int c = it * 32 + lane;
            if (c < NCOLS) {
                float d = pp[c] - pt[c];
                bool five; int col;
                if (c < 41) { col = c; five = ((c & 3) == 0); }
                else {
                    int j = c - 41; col = j;
                    five = ((j & 3) == 3) || (((j & 3) == 0) && (j != 40));
                }
                float w = five ? 5.0f : 1.0f;
                if (col >= cut) w *= 0.1f;
                acc = fmaf(d * d, w, acc);
            }
        }
    }

    // ---- block reduction ----
    #pragma unroll
    for (int o = 16; o > 0; o >>= 1)
        acc += __shfl_down_sync(0xffffffffu, acc, o);

    __shared__ float smem[NTHREADS / 32];
    __shared__ bool  s_last;
    if (lane == 0) smem[warp] = acc;
    __syncthreads();
    if (warp == 0) {
        float v = (lane < (NTHREADS / 32)) ? smem[lane] : 0.0f;
        #pragma unroll
        for (int o = 4; o > 0; o >>= 1)
            v += __shfl_down_sync(0xffffffffu, v, o);
        if (lane == 0) {
            g_part[blockIdx.x] = v;
            __threadfence();
            unsigned n = atomicAdd(&g_count, 1u);
            s_last = (n == NBLOCKS - 1);
        }
    }
    __syncthreads();

    // ---- last block: deterministic final reduction (cold path) ----
    if (s_last) {
        __threadfence();
        double a = 0.0;
        for (int i = threadIdx.x; i < NBLOCKS; i += NTHREADS)
            a += (double)((volatile float*)g_part)[i];
        #pragma unroll
        for (int o = 16; o > 0; o >>= 1)
            a += __shfl_down_sync(0xffffffffu, a, o);
        __shared__ double sd[NTHREADS / 32];
        if (lane == 0) sd[warp] = a;
        __syncthreads();
        if (warp == 0) {
            a = (lane < (NTHREADS / 32)) ? sd[lane] : 0.0;
            #pragma unroll
            for (int o = 4; o > 0; o >>= 1)
                a += __shfl_down_sync(0xffffffffu, a, o);
            if (lane == 0) {
                out[0]  = (float)(a * inv_total);
                g_count = 0;
            }
        }
    }
}

extern "C" void kernel_launch(void* const* d_in, const int* in_sizes, int n_in,
                              void* d_out, int out_size)
{
    const float* pred = (const float*)d_in[0];
    const float* targ = (const float*)d_in[1];
    const float* inp  = (const float*)d_in[2];
    float* out = (float*)d_out;

    const int B = in_sizes[0] / NCOLS;   // 500000

    wmse_kernel<<<NBLOCKS, NTHREADS>>>(pred, targ, inp, B,
                                       1.0 / ((double)B * NCOLS), out);
}

// round 6
// speedup vs baseline: 1.0995x; 1.0957x over previous
#include <cuda_runtime.h>

// ObservabilityWeightedMSE — weighted-MSE reduction, two launches.
// d_in[0]=predictions [500000,82] f32, d_in[1]=targets [500000,82] f32,
// d_in[2]=inputs [500000,400] f32. Output: scalar f32.
// R3 lesson: occupancy-bound at >32 regs -> __launch_bounds__(256,8).
// R4/R5 lesson: cache policy + occupancy were NOT the 182us cause.
// R6 experiment: remove fused tail (threadfence + single-address atomic per
// block serialized the kernel end); blocks just store partials, tiny second
// kernel reduces them.

#define THRESH   1e-4f
#define NCOLS    82
#define ROW_IN   400
#define NBLOCKS  1184
#define NTHREADS 256

__device__ float g_part[NBLOCKS];

__global__ void __launch_bounds__(NTHREADS, 8)   // cap regs at 32: 8 blocks/SM
wmse_kernel(const float* __restrict__ pred,
            const float* __restrict__ targ,
            const float* __restrict__ inp,
            int B)
{
    const int lane  = threadIdx.x & 31;
    const int warp  = threadIdx.x >> 5;
    const int gwarp = blockIdx.x * (NTHREADS / 32) + warp;
    const int nwarp = NBLOCKS * (NTHREADS / 32);

    // lane-constant geometry for the inputs magnitude slice
    const int  n0   = lane / 5, p0 = lane % 5;      // float4 idx = lane
    const int  i1   = 32 + lane;
    const int  n1   = i1 / 5,  p1 = i1 % 5;         // float4 idx = 32+lane
    const bool has1 = (i1 < 50);                    // lanes 0..17
    const int  off0 = n0 * 40 + p0 * 4;
    const int  off1 = n1 * 40 + p1 * 4;

    float acc = 0.0f;

    for (int r = gwarp; r < B; r += nwarp) {
        const float* pin = inp + (size_t)r * ROW_IN;

        // ---- node-below test: below[n] <=> max of 20 magnitudes < THRESH ----
        float4 a0 = *(const float4*)(pin + off0);
        unsigned ok = 0;
        if (fmaxf(fmaxf(a0.x, a0.y), fmaxf(a0.z, a0.w)) >= THRESH)
            ok = 1u << n0;
        if (has1) {
            float4 a1 = *(const float4*)(pin + off1);
            if (fmaxf(fmaxf(a1.x, a1.y), fmaxf(a1.z, a1.w)) >= THRESH)
                ok |= 1u << n1;
        }
        unsigned below = (~__reduce_or_sync(0xffffffffu, ok)) & 0x3FFu;
        const int cut = below ? (__ffs(below) << 2) : 1000;

        // ---- weighted MSE over 82 columns, coalesced scalar loads ----
        const float* pp = pred + (size_t)r * NCOLS;
        const float* pt = targ + (size_t)r * NCOLS;
        #pragma unroll
        for (int it = 0; it < 3; ++it) {
            int c = it * 32 + lane;
            if (c < NCOLS) {
                float d = pp[c] - pt[c];
                bool five; int col;
                if (c < 41) { col = c; five = ((c & 3) == 0); }
                else {
                    int j = c - 41; col = j;
                    five = ((j & 3) == 3) || (((j & 3) == 0) && (j != 40));
                }
                float w = five ? 5.0f : 1.0f;
                if (col >= cut) w *= 0.1f;
                acc = fmaf(d * d, w, acc);
            }
        }
    }

    // ---- block reduction -> one plain store per block (no fence/atomic) ----
    #pragma unroll
    for (int o = 16; o > 0; o >>= 1)
        acc += __shfl_down_sync(0xffffffffu, acc, o);

    __shared__ float smem[NTHREADS / 32];
    if (lane == 0) smem[warp] = acc;
    __syncthreads();
    if (warp == 0) {
        float v = (lane < (NTHREADS / 32)) ? smem[lane] : 0.0f;
        #pragma unroll
        for (int o = 4; o > 0; o >>= 1)
            v += __shfl_down_sync(0xffffffffu, v, o);
        if (lane == 0) g_part[blockIdx.x] = v;
    }
}

__global__ void __launch_bounds__(1024)
finalize_kernel(float* __restrict__ out, double inv_total)
{
    const int lane = threadIdx.x & 31, w = threadIdx.x >> 5;
    double a = 0.0;
    for (int i = threadIdx.x; i < NBLOCKS; i += 1024)
        a += (double)g_part[i];
    #pragma unroll
    for (int o = 16; o > 0; o >>= 1)
        a += __shfl_down_sync(0xffffffffu, a, o);
    __shared__ double sd[32];
    if (lane == 0) sd[w] = a;
    __syncthreads();
    if (w == 0) {
        a = sd[lane];
        #pragma unroll
        for (int o = 16; o > 0; o >>= 1)
            a += __shfl_down_sync(0xffffffffu, a, o);
        if (lane == 0) out[0] = (float)(a * inv_total);
    }
}

extern "C" void kernel_launch(void* const* d_in, const int* in_sizes, int n_in,
                              void* d_out, int out_size)
{
    const float* pred = (const float*)d_in[0];
    const float* targ = (const float*)d_in[1];
    const float* inp  = (const float*)d_in[2];
    float* out = (float*)d_out;

    const int B = in_sizes[0] / NCOLS;   // 500000

    wmse_kernel<<<NBLOCKS, NTHREADS>>>(pred, targ, inp, B);
    finalize_kernel<<<1, 1024>>>(out, 1.0 / ((double)B * NCOLS));
}